// round 1
// baseline (speedup 1.0000x reference)
#include <cuda_runtime.h>
#include <cstdint>
#include <math.h>

#define BB 512
#define TT 255
#define DD 128
#define HH 1024
#define GG 4096   // 4*H
#define KC 1152   // D + H

// ---------------- scratch (device globals: no allocation allowed) ----------
__device__ __align__(16) float g_a[BB * DD];                 // attention weights
__device__ __align__(16) float g_h[BB * HH];                 // h_t
__device__ __align__(16) float g_c[BB * HH];                 // c_t
__device__ __align__(16) float g_gates[(size_t)BB * GG];     // per-step gate preacts
__device__ __align__(16) float g_wcat[(size_t)GG * KC];      // [W_ih | W_hh], tf32-rounded

__device__ __forceinline__ float to_tf32(float x) {
    uint32_t u;
    asm("cvt.rna.tf32.f32 %0, %1;" : "=r"(u) : "f"(x));
    return __uint_as_float(u);
}

// ---------------- kernel 1: e_x + softmax -> g_a ---------------------------
__global__ void attn_kernel(const float* __restrict__ x, const float* __restrict__ wattn) {
    int b = blockIdx.x, d = threadIdx.x;  // 128 threads
    __shared__ float swx[TT];
    __shared__ float red[8];
    for (int i = d; i < TT; i += DD) swx[i] = wattn[2 * HH + i];
    __syncthreads();
    const float* xb = x + (size_t)b * TT * DD + d;
    float e = 0.f;
#pragma unroll 5
    for (int t = 0; t < TT; t++) e += xb[(size_t)t * DD] * swx[t];

    int lane = d & 31, warp = d >> 5;
    float m = e;
#pragma unroll
    for (int o = 16; o; o >>= 1) m = fmaxf(m, __shfl_xor_sync(0xffffffffu, m, o));
    if (!lane) red[warp] = m;
    __syncthreads();
    m = fmaxf(fmaxf(red[0], red[1]), fmaxf(red[2], red[3]));
    float ex = expf(e - m);
    float s = ex;
#pragma unroll
    for (int o = 16; o; o >>= 1) s += __shfl_xor_sync(0xffffffffu, s, o);
    if (!lane) red[4 + warp] = s;
    __syncthreads();
    s = red[4] + red[5] + red[6] + red[7];
    g_a[b * DD + d] = ex / s;
}

// ---------------- kernel 2: w = a * x -> output region 1 -------------------
__global__ void weight_kernel(const float* __restrict__ x, float* __restrict__ outw) {
    size_t n4 = (size_t)BB * TT * DD / 4;
    const float4* x4 = (const float4*)x;
    const float4* a4 = (const float4*)g_a;
    float4* o4 = (float4*)outw;
    for (size_t i = (size_t)blockIdx.x * blockDim.x + threadIdx.x; i < n4;
         i += (size_t)gridDim.x * blockDim.x) {
        size_t b = i / (TT * 32);
        int d4 = (int)(i % 32);
        float4 av = a4[b * 32 + d4];
        float4 xv = x4[i];
        float4 w;
        w.x = av.x * xv.x; w.y = av.y * xv.y; w.z = av.z * xv.z; w.w = av.w * xv.w;
        o4[i] = w;
    }
}

// ---------------- kernel 3: build concatenated tf32 weights ----------------
__global__ void prep_kernel(const float* __restrict__ wih, const float* __restrict__ whh) {
    size_t n = (size_t)GG * KC;
    for (size_t i = (size_t)blockIdx.x * blockDim.x + threadIdx.x; i < n;
         i += (size_t)gridDim.x * blockDim.x) {
        int k = (int)(i % KC);
        int r = (int)(i / KC);
        float v = (k < DD) ? wih[(size_t)r * DD + k] : whh[(size_t)r * HH + (k - DD)];
        g_wcat[i] = to_tf32(v);
    }
}

// ---------------- kernel 4: zero h,c ---------------------------------------
__global__ void zero_kernel() {
    int i = blockIdx.x * blockDim.x + threadIdx.x;
    if (i < BB * HH) { g_h[i] = 0.f; g_c[i] = 0.f; }
}

// ---------------- kernel 5: per-step GEMM (tf32 mma.sync) ------------------
// gates[512,4096] = [w_t | h] (512,1152) @ wcat^T (1152,4096)
__global__ __launch_bounds__(256, 2) void step_gemm(const float* __restrict__ outw, int t) {
    __shared__ float As[128][36];
    __shared__ float Bs[128][36];
    int tid = threadIdx.x;
    int warp = tid >> 5, lane = tid & 31;
    int wm = warp & 1, wn = warp >> 1;          // 2 warps M x 4 warps N
    int bm0 = blockIdx.y * 128, bn0 = blockIdx.x * 128;

    float acc[4][4][4];
#pragma unroll
    for (int i = 0; i < 4; i++)
#pragma unroll
        for (int j = 0; j < 4; j++)
#pragma unroll
            for (int r = 0; r < 4; r++) acc[i][j][r] = 0.f;

    int lr = tid >> 3;          // 0..31 (row within 32-row pass)
    int lc = (tid & 7) << 2;    // 0,4,...,28

    for (int ks = 0; ks < KC; ks += 32) {
        // stage A tile (128x32) with tf32 rounding
#pragma unroll
        for (int p = 0; p < 4; p++) {
            int m = lr + p * 32;
            int gm = bm0 + m;
            const float* src;
            if (ks < DD) src = outw + ((size_t)gm * TT + t) * DD + ks + lc;
            else         src = g_h + (size_t)gm * HH + (ks - DD) + lc;
            float4 v = *(const float4*)src;
            float4 w = make_float4(to_tf32(v.x), to_tf32(v.y), to_tf32(v.z), to_tf32(v.w));
            *(float4*)&As[m][lc] = w;
        }
        // stage B tile (128x32), already tf32-rounded
#pragma unroll
        for (int p = 0; p < 4; p++) {
            int n = lr + p * 32;
            float4 v = *(const float4*)&g_wcat[(size_t)(bn0 + n) * KC + ks + lc];
            *(float4*)&Bs[n][lc] = v;
        }
        __syncthreads();

#pragma unroll
        for (int kk = 0; kk < 32; kk += 8) {
            uint32_t af[4][4], bf[4][2];
#pragma unroll
            for (int mt = 0; mt < 4; mt++) {
                int r0 = wm * 64 + mt * 16 + (lane >> 2);
                int c0 = kk + (lane & 3);
                af[mt][0] = __float_as_uint(As[r0][c0]);
                af[mt][1] = __float_as_uint(As[r0 + 8][c0]);
                af[mt][2] = __float_as_uint(As[r0][c0 + 4]);
                af[mt][3] = __float_as_uint(As[r0 + 8][c0 + 4]);
            }
#pragma unroll
            for (int nt = 0; nt < 4; nt++) {
                int n0 = wn * 32 + nt * 8 + (lane >> 2);
                int c0 = kk + (lane & 3);
                bf[nt][0] = __float_as_uint(Bs[n0][c0]);
                bf[nt][1] = __float_as_uint(Bs[n0][c0 + 4]);
            }
#pragma unroll
            for (int mt = 0; mt < 4; mt++)
#pragma unroll
                for (int nt = 0; nt < 4; nt++)
                    asm volatile(
                        "mma.sync.aligned.m16n8k8.row.col.f32.tf32.tf32.f32 "
                        "{%0,%1,%2,%3}, {%4,%5,%6,%7}, {%8,%9}, {%0,%1,%2,%3};"
                        : "+f"(acc[mt][nt][0]), "+f"(acc[mt][nt][1]),
                          "+f"(acc[mt][nt][2]), "+f"(acc[mt][nt][3])
                        : "r"(af[mt][0]), "r"(af[mt][1]), "r"(af[mt][2]), "r"(af[mt][3]),
                          "r"(bf[nt][0]), "r"(bf[nt][1]));
        }
        __syncthreads();
    }

    // epilogue
#pragma unroll
    for (int mt = 0; mt < 4; mt++) {
        int r0 = bm0 + wm * 64 + mt * 16 + (lane >> 2);
#pragma unroll
        for (int nt = 0; nt < 4; nt++) {
            int c0 = bn0 + wn * 32 + nt * 8 + ((lane & 3) << 1);
            *(float2*)&g_gates[(size_t)r0 * GG + c0] =
                make_float2(acc[mt][nt][0], acc[mt][nt][1]);
            *(float2*)&g_gates[(size_t)(r0 + 8) * GG + c0] =
                make_float2(acc[mt][nt][2], acc[mt][nt][3]);
        }
    }
}

// ---------------- kernel 6: pointwise LSTM update --------------------------
__global__ void step_point(const float* __restrict__ bih, const float* __restrict__ bhh,
                           float* __restrict__ outh, int t) {
    int idx = blockIdx.x * blockDim.x + threadIdx.x;
    if (idx >= BB * HH) return;
    int b = idx >> 10, j = idx & 1023;
    const float* g = g_gates + (size_t)b * GG;
    float gi = g[j]        + bih[j]        + bhh[j];
    float gf = g[j + 1024] + bih[j + 1024] + bhh[j + 1024];
    float gc = g[j + 2048] + bih[j + 2048] + bhh[j + 2048];
    float go = g[j + 3072] + bih[j + 3072] + bhh[j + 3072];
    float c = g_c[idx];
    float si = 1.f / (1.f + expf(-gi));
    float sf = 1.f / (1.f + expf(-gf));
    float so = 1.f / (1.f + expf(-go));
    float cn = sf * c + si * tanhf(gc);
    float hn = so * tanhf(cn);
    g_c[idx] = cn;
    g_h[idx] = hn;
    outh[((size_t)b * TT + t) * HH + j] = hn;
}

// ---------------- launch ----------------------------------------------------
extern "C" void kernel_launch(void* const* d_in, const int* in_sizes, int n_in,
                              void* d_out, int out_size) {
    (void)in_sizes; (void)n_in; (void)out_size;
    const float* x     = (const float*)d_in[0];
    const float* wattn = (const float*)d_in[1];
    // d_in[2] = b_attn: provably irrelevant (softmax shift invariance)
    const float* wih   = (const float*)d_in[3];
    const float* whh   = (const float*)d_in[4];
    const float* bih   = (const float*)d_in[5];
    const float* bhh   = (const float*)d_in[6];

    float* out  = (float*)d_out;
    float* outw = out;                               // (B, T, D)
    float* outh = out + (size_t)BB * TT * DD;        // (B, T, H)

    attn_kernel<<<BB, DD>>>(x, wattn);
    weight_kernel<<<2048, 256>>>(x, outw);
    prep_kernel<<<2048, 256>>>(wih, whh);
    zero_kernel<<<(BB * HH + 255) / 256, 256>>>();

    dim3 gemm_grid(32, 4);  // N/128 x M/128
    for (int t = 0; t < TT; t++) {
        step_gemm<<<gemm_grid, 256>>>(outw, t);
        step_point<<<(BB * HH + 255) / 256, 256>>>(bih, bhh, outh, t);
    }
}